// round 16
// baseline (speedup 1.0000x reference)
#include <cuda_runtime.h>
#include <math.h>

#define NQ   10
#define DIM  1024
#define NP   64
#define DF   10
#define NL   5
#define NBLK 136          // 16*17/2 triangle tiles; single wave (<148 SMs)
#define NT   256

#define TWOPI   6.2831853071795864769f
#define INV2PI  0.15915494309189533577f
#define EXS     12        // exchange stride in floats (48B, float4-aligned)

// Scratch (no device allocations allowed)
__device__ __align__(16) float2 g_states[NP * DIM];   // psi(x_p), 512 KB
__device__ __align__(16) double2 g_part[NBLK];        // per-block (kp, kk)
__device__ unsigned g_ready = 0;                      // sim-done counter (target 64)
__device__ unsigned g_done  = 0;                      // gram-done ticket (target NBLK)

__device__ __forceinline__ void cmul(float ar, float ai, float br, float bi,
                                     float& cr, float& ci)
{
    cr = ar * br - ai * bi;
    ci = ar * bi + ai * br;
}

// release-add: makes all my prior writes visible before the add lands
__device__ __forceinline__ void red_release_add(unsigned* p, unsigned v)
{
    asm volatile("red.release.gpu.add.u32 [%0], %1;" :: "l"(p), "r"(v) : "memory");
}
// acquire-load: orders my subsequent reads after the observed release
__device__ __forceinline__ unsigned ld_acquire(unsigned* p)
{
    unsigned v;
    asm volatile("ld.acquire.gpu.u32 %0, [%1];" : "=r"(v) : "l"(p) : "memory");
    return v;
}
// acq_rel fetch-add ticket: releases my writes, acquires everyone else's
__device__ __forceinline__ unsigned atom_acqrel_add(unsigned* p, unsigned v)
{
    unsigned old;
    asm volatile("atom.acq_rel.gpu.add.u32 %0, [%1], %2;"
                 : "=r"(old) : "l"(p), "r"(v) : "memory");
    return old;
}

// ============================================================================
// Fused single kernel — R15 champion + release/acquire handoff (no membars):
//  phase 1: blocks 0-63 simulate psi(x_p), one point per block, A=4/thread.
//           FINAL layer's crz-ring diagonal skipped (same unitary diagonal
//           for all points -> cancels exactly in every |<a|b>|^2).
//  wait:    acquire-load busy-poll until g_ready == 64; tile decode and
//           label loads hoisted before the poll.
//  phase 2: 136 blocks, one 4x4 triangle tile, 2 pairs/warp.
//  tail:    last block (acq_rel ticket), warp 0 only, fixed-order reduce.
// ============================================================================
__global__ __launch_bounds__(NT) void fused_kernel(
    const float* __restrict__ data,     // (NP, DF)
    const float* __restrict__ labels,   // (NP,)
    const float* __restrict__ params,   // (NL, 2, NQ)
    float* __restrict__ out)
{
    __shared__ float Ug[NL][NQ][8];     // composed gates U = RY*RZ*H (incl 1/sqrt2)
    __shared__ float phis[NL][NQ];
    __shared__ float2 Cx[NL * 64];      // exchange coefs [l][w][pw]
    __shared__ __align__(16) float ebuf[2][NT * EXS];   // 24 KB
    __shared__ double wacc[8][2];       // per-warp gram partials
    __shared__ unsigned s_last;

    const int p    = blockIdx.x;
    const int t    = threadIdx.x;
    const int lane = t & 31;
    const int w    = t >> 5;            // 8 warps

    // ---------------- phase 1: simulation (blocks 0-63) ----------------
    if (p < NP) {
        if (t < NL * NQ) {
            const int l = t / NQ, q = t % NQ;
            const float alpha = data[p * DF + (NQ - 1 - q)];
            const float theta = params[l * 2 * NQ + q];
            float s, c, sa, ca;
            __sincosf(0.5f * theta, &s, &c);
            __sincosf(0.5f * alpha, &sa, &ca);
            const float INV_S2 = 0.70710678118654752440f;
            float* U = &Ug[l][q][0];
            U[0] = (c - s) * ca * INV_S2;   U[1] = -(c + s) * sa * INV_S2;  // u00
            U[2] = (c + s) * ca * INV_S2;   U[3] =  (s - c) * sa * INV_S2;  // u01
            U[4] = (s + c) * ca * INV_S2;   U[5] =  (c - s) * sa * INV_S2;  // u10
            U[6] = (s - c) * ca * INV_S2;   U[7] = -(s + c) * sa * INV_S2;  // u11
            phis[l][q] = params[l * 2 * NQ + NQ + q];
        }
        __syncthreads();

        // exchange coefficients Cx[l][ww][pw] = U5[b5][pw0]*U6[b6][pw1]*U7[b7][pw2]
        for (int e = t; e < NL * 64; e += NT) {
            const int l  = e >> 6;
            const int ww = (e >> 3) & 7;
            const int pw = e & 7;
            const int b5 = ww & 1, b6 = (ww >> 1) & 1, b7 = (ww >> 2) & 1;
            const float* U5 = &Ug[l][5][(2 * b5 + (pw & 1)) * 2];
            const float* U6 = &Ug[l][6][(2 * b6 + ((pw >> 1) & 1)) * 2];
            const float* U7 = &Ug[l][7][(2 * b7 + (pw >> 2)) * 2];
            float t1r, t1i, cr, ci;
            cmul(U5[0], U5[1], U6[0], U6[1], t1r, t1i);
            cmul(t1r, t1i, U7[0], U7[1], cr, ci);
            Cx[e] = make_float2(cr, ci);
        }

        float cring[7];
        #pragma unroll
        for (int m = 0; m < 7; ++m) {
            float bm  = (float)((t >> m) & 1);
            float bm1 = (float)((t >> (m + 1)) & 1);
            cring[m] = bm * (bm1 - 0.5f);
        }
        const float c7  = (float)((t >> 7) & 1);
        const float c9a = (float)(t & 1) - 0.5f;
        __syncthreads();

        float re[4], im[4];

        // layer 0 from |0>: amp = prod_q U_q[b_q][0]
        {
            float cr = 1.f, ci = 0.f;
            #pragma unroll
            for (int q = 0; q < 8; ++q) {
                int b = (t >> q) & 1;
                const float* Uq = &Ug[0][q][0];
                float nr, ni;
                cmul(cr, ci, Uq[b * 4], Uq[b * 4 + 1], nr, ni);
                cr = nr;  ci = ni;
            }
            float c8r[2], c8i[2];
            #pragma unroll
            for (int j = 0; j < 2; ++j)
                cmul(cr, ci, Ug[0][8][j * 4], Ug[0][8][j * 4 + 1], c8r[j], c8i[j]);
            #pragma unroll
            for (int r = 0; r < 4; ++r)
                cmul(c8r[r & 1], c8i[r & 1],
                     Ug[0][9][(r >> 1) * 4], Ug[0][9][(r >> 1) * 4 + 1],
                     re[r], im[r]);
        }

        #pragma unroll 1
        for (int l = 0; ; ) {
            // crz ring diagonal, layer l — FINAL layer's ring cancels: skip
            if (l < NL - 1) {
                float angT = 0.f;
                #pragma unroll
                for (int m = 0; m < 7; ++m) angT = fmaf(cring[m], phis[l][m], angT);
                const float p7 = phis[l][7], p8 = phis[l][8], p9 = phis[l][9];
                #pragma unroll
                for (int r = 0; r < 4; ++r) {
                    float f8 = (float)(r & 1), f9 = (float)(r >> 1);
                    float ang = angT;
                    ang = fmaf(c7 * (f8 - 0.5f), p7, ang);
                    ang = fmaf(f8 * (f9 - 0.5f), p8, ang);
                    ang = fmaf(f9 * c9a,         p9, ang);
                    ang = fmaf(-TWOPI, rintf(ang * INV2PI), ang);
                    float s, c;
                    __sincosf(ang, &s, &c);
                    float nr = re[r] * c - im[r] * s;
                    im[r]    = re[r] * s + im[r] * c;
                    re[r]    = nr;
                }
            }
            if (++l >= NL) break;

            // lane qubits 0-4 (shfl butterflies)
            #pragma unroll
            for (int q = 0; q < 5; ++q) {
                const int b = (lane >> q) & 1;
                const float* Uq = &Ug[l][q][0];
                const float ur = Uq[b * 6],     ui = Uq[b * 6 + 1];
                const float vr = Uq[2 + b * 2], vi = Uq[3 + b * 2];
                #pragma unroll
                for (int r = 0; r < 4; ++r) {
                    float pre = __shfl_xor_sync(0xffffffffu, re[r], 1 << q);
                    float pim = __shfl_xor_sync(0xffffffffu, im[r], 1 << q);
                    float nr = ur * re[r] - ui * im[r] + vr * pre - vi * pim;
                    float ni = ur * im[r] + ui * re[r] + vr * pim + vi * pre;
                    re[r] = nr;  im[r] = ni;
                }
            }
            // reg qubits 8, 9
            {
                const float* U8 = &Ug[l][8][0];
                #pragma unroll
                for (int j = 0; j < 4; j += 2) {
                    float a0r = re[j], a0i = im[j], a1r = re[j+1], a1i = im[j+1];
                    re[j]   = U8[0]*a0r - U8[1]*a0i + U8[2]*a1r - U8[3]*a1i;
                    im[j]   = U8[0]*a0i + U8[1]*a0r + U8[2]*a1i + U8[3]*a1r;
                    re[j+1] = U8[4]*a0r - U8[5]*a0i + U8[6]*a1r - U8[7]*a1i;
                    im[j+1] = U8[4]*a0i + U8[5]*a0r + U8[6]*a1i + U8[7]*a1r;
                }
                const float* U9 = &Ug[l][9][0];
                #pragma unroll
                for (int j = 0; j < 2; ++j) {
                    float a0r = re[j], a0i = im[j], a1r = re[j+2], a1i = im[j+2];
                    re[j]   = U9[0]*a0r - U9[1]*a0i + U9[2]*a1r - U9[3]*a1i;
                    im[j]   = U9[0]*a0i + U9[1]*a0r + U9[2]*a1i + U9[3]*a1r;
                    re[j+2] = U9[4]*a0r - U9[5]*a0i + U9[6]*a1r - U9[7]*a1i;
                    im[j+2] = U9[4]*a0i + U9[5]*a0r + U9[6]*a1i + U9[7]*a1r;
                }
            }
            // warp qubits 5-7: flat 8-way exchange (precomputed coefs)
            {
                float* my = &ebuf[l & 1][t * EXS];
                *(float4*)(my)     = make_float4(re[0], re[1], re[2], re[3]);
                *(float4*)(my + 4) = make_float4(im[0], im[1], im[2], im[3]);
                __syncthreads();
                float nr[4] = {0.f,0.f,0.f,0.f}, ni[4] = {0.f,0.f,0.f,0.f};
                const float2* cw = &Cx[(l << 6) | (w << 3)];
                #pragma unroll
                for (int pw = 0; pw < 8; ++pw) {
                    const float* pr = &ebuf[l & 1][((pw << 5) | lane) * EXS];
                    float4 vre = *(const float4*)(pr);
                    float4 vim = *(const float4*)(pr + 4);
                    const float cr = cw[pw].x, cc = cw[pw].y;
                    nr[0] += cr*vre.x - cc*vim.x;  ni[0] += cr*vim.x + cc*vre.x;
                    nr[1] += cr*vre.y - cc*vim.y;  ni[1] += cr*vim.y + cc*vre.y;
                    nr[2] += cr*vre.z - cc*vim.z;  ni[2] += cr*vim.z + cc*vre.z;
                    nr[3] += cr*vre.w - cc*vim.w;  ni[3] += cr*vim.w + cc*vre.w;
                }
                #pragma unroll
                for (int r = 0; r < 4; ++r) { re[r] = nr[r]; im[r] = ni[r]; }
            }
        }

        #pragma unroll
        for (int r = 0; r < 4; ++r)
            g_states[p * DIM + (r << 8) + t] = make_float2(re[r], im[r]);

        __syncthreads();                 // all state writes done
        if (t == 0) red_release_add(&g_ready, 1u);   // release covers the STGs
    }

    // ---------------- tile decode + label prefetch (independent of wait) ----------------
    int rem = blockIdx.x, gi = 0;
    while (rem >= 16 - gi) { rem -= 16 - gi; ++gi; }
    const int gj = gi + rem;
    const int i  = gi * 4 + (w >> 1);
    const int j0 = gj * 4 + 2 * (w & 1);
    const double f = (gi == gj) ? 1.0 : 2.0;
    const float li_f  = labels[i];
    const float lj0_f = labels[j0];
    const float lj1_f = labels[j0 + 1];

    // ---------------- wait: acquire-load busy-poll ----------------
    if (t == 0) {
        while (ld_acquire(&g_ready) < NP) { }
    }
    __syncthreads();

    // ---------------- phase 2: gram tile + local KTA contribution ----------------
    {
        const float2* __restrict__ A  = g_states + i * DIM;
        const float2* __restrict__ B0 = g_states + j0 * DIM;
        const float2* __restrict__ B1 = g_states + (j0 + 1) * DIM;

        float r0 = 0.f, i0a = 0.f, r1 = 0.f, i1a = 0.f;
        #pragma unroll 8
        for (int kk = 0; kk < 16; ++kk) {
            const int k = kk * 64 + lane * 2;
            float4 a  = *(const float4*)&A[k];
            float4 b0 = *(const float4*)&B0[k];
            float4 b1 = *(const float4*)&B1[k];
            r0  += b0.x*a.x + b0.y*a.y + b0.z*a.z + b0.w*a.w;
            i0a += b0.x*a.y - b0.y*a.x + b0.z*a.w - b0.w*a.z;
            r1  += b1.x*a.x + b1.y*a.y + b1.z*a.z + b1.w*a.w;
            i1a += b1.x*a.y - b1.y*a.x + b1.z*a.w - b1.w*a.z;
        }
        #pragma unroll
        for (int off = 16; off; off >>= 1) {
            r0  += __shfl_down_sync(0xffffffffu, r0,  off);
            i0a += __shfl_down_sync(0xffffffffu, i0a, off);
            r1  += __shfl_down_sync(0xffffffffu, r1,  off);
            i1a += __shfl_down_sync(0xffffffffu, i1a, off);
        }
        if (lane == 0) {
            double k0 = (double)r0 * r0 + (double)i0a * i0a;
            double k1 = (double)r1 * r1 + (double)i1a * i1a;
            double li  = (double)li_f;
            wacc[w][0] = f * (li * (double)lj0_f * k0 + li * (double)lj1_f * k1);
            wacc[w][1] = f * (k0 * k0 + k1 * k1);
        }
        __syncthreads();
        if (t == 0) {
            double kp = 0.0, kk = 0.0;
            #pragma unroll
            for (int ww = 0; ww < 8; ++ww) { kp += wacc[ww][0]; kk += wacc[ww][1]; }
            g_part[blockIdx.x] = make_double2(kp, kk);
            // acq_rel ticket: releases my g_part write, acquires everyone else's
            s_last = (atom_acqrel_add(&g_done, 1u) == NBLK - 1) ? 1u : 0u;
        }
    }
    __syncthreads();

    // ---------------- tail: last block, warp 0 only, fixed-order reduce ----------------
    if (s_last && w == 0) {
        double kp = 0.0, kk = 0.0;
        #pragma unroll
        for (int e = lane; e < NBLK; e += 32) {     // fixed order per lane
            double2 v = g_part[e];
            kp += v.x;  kk += v.y;
        }
        float l0 = labels[lane], l1 = labels[lane + 32];
        double sl2 = (double)(l0 * l0 + l1 * l1);
        #pragma unroll
        for (int off = 16; off; off >>= 1) {
            kp  += __shfl_down_sync(0xffffffffu, kp,  off);
            kk  += __shfl_down_sync(0xffffffffu, kk,  off);
            sl2 += __shfl_down_sync(0xffffffffu, sl2, off);
        }
        if (lane == 0) {
            out[0] = (float)(kp / sqrt(kk * sl2 * sl2));
            g_ready = 0;          // reset for next graph replay
            g_done  = 0;
            __threadfence();      // publish resets before kernel end
        }
    }
}

// ----------------------------------------------------------------------------
extern "C" void kernel_launch(void* const* d_in, const int* in_sizes, int n_in,
                              void* d_out, int out_size)
{
    const float* data   = (const float*)d_in[0];   // (64, 10)
    const float* labels = (const float*)d_in[1];   // (64,)
    const float* params = (const float*)d_in[2];   // (5, 2, 10)
    float* out = (float*)d_out;

    fused_kernel<<<NBLK, NT>>>(data, labels, params, out);
}